// round 5
// baseline (speedup 1.0000x reference)
#include <cuda_runtime.h>
#include <math.h>

#define Bc   2
#define DHc  64
#define DWc  150
#define Nc   9600
#define BNc  19200
#define Kc   10
#define PI_F 3.14159265358979323846f

// ---------------- scratch (device-symbol access ONLY from device code) ----------------
__device__ float d_px[BNc], d_py[BNc], d_pz[BNc], d_sq[BNc];
__device__ int   d_edges[BNc * Kc];
__device__ float d_h1[BNc * 128], d_res1[BNc * 128], d_g1[BNc * 128];
__device__ float d_es[BNc], d_ed[BNc];
__device__ float d_h2[BNc * 256], d_res2[BNc * 256], d_g2[BNc * 256];
__device__ float d_act[BNc * 64];
__device__ float d_vlad[Bc * 256 * 64];
__device__ float d_colsq[Bc * 64];
__device__ float d_y[Bc * 256];

// ---------------- 1. spherical -> cartesian points ----------------
__global__ void pts_kernel(const float* __restrict__ depth) {
    int gn = blockIdx.x * 256 + threadIdx.x;
    if (gn >= BNc) return;
    int n = gn % Nc;
    int i = n / DWc;
    int j = n % DWc;
    float theta = -PI_F + (float)j * (2.0f * PI_F / 149.0f);
    float phi   = -0.5f * PI_F + (float)i * (PI_F / 63.0f);
    float r = depth[gn];
    float cp = cosf(phi), sp = sinf(phi);
    float st = sinf(theta), ct = cosf(theta);
    float x = r * cp * st;
    float y = r * sp;
    float z = r * cp * ct;
    d_px[gn] = x; d_py[gn] = y; d_pz[gn] = z;
    d_sq[gn] = x * x + y * y + z * z;
}

// ---------------- 2. brute-force kNN (K=10 smallest d2) ----------------
__global__ void knn_kernel() {
    int b  = blockIdx.x / 38;
    int qb = blockIdx.x % 38;
    int q  = qb * 256 + threadIdx.x;
    bool valid = (q < Nc);
    int base = b * Nc;

    float qx = 0.f, qy = 0.f, qz = 0.f, qs = 0.f;
    if (valid) {
        qx = d_px[base + q]; qy = d_py[base + q];
        qz = d_pz[base + q]; qs = d_sq[base + q];
    }

    __shared__ float sx[256], sy[256], sz[256], ss[256];

    float bd[Kc]; int bi[Kc];
#pragma unroll
    for (int k = 0; k < Kc; k++) { bd[k] = 3.4e38f; bi[k] = 0; }
    float worst = 3.4e38f;

    for (int t0 = 0; t0 < Nc; t0 += 256) {
        int m = t0 + threadIdx.x;
        if (m < Nc) {
            sx[threadIdx.x] = d_px[base + m];
            sy[threadIdx.x] = d_py[base + m];
            sz[threadIdx.x] = d_pz[base + m];
            ss[threadIdx.x] = d_sq[base + m];
        }
        __syncthreads();
        int lim = Nc - t0; if (lim > 256) lim = 256;
        if (valid) {
            for (int c = 0; c < lim; c++) {
                float d2 = qs + ss[c] - 2.0f * (qx * sx[c] + qy * sy[c] + qz * sz[c]);
                if (d2 < worst) {
                    bd[Kc - 1] = d2; bi[Kc - 1] = t0 + c;
#pragma unroll
                    for (int p = Kc - 1; p > 0; --p) {
                        if (bd[p] < bd[p - 1]) {
                            float td = bd[p]; bd[p] = bd[p - 1]; bd[p - 1] = td;
                            int   ti = bi[p]; bi[p] = bi[p - 1]; bi[p - 1] = ti;
                        }
                    }
                    worst = bd[Kc - 1];
                }
            }
        }
        __syncthreads();
    }
    if (valid) {
#pragma unroll
        for (int k = 0; k < Kc; k++) d_edges[(base + q) * Kc + k] = bi[k];
    }
}

// ---------------- 3a. GAT1 projection (3 -> 128) + e_src/e_dst + residual ----------------
__global__ void gat1_kernel(const float* __restrict__ W,
                            const float* __restrict__ as_,
                            const float* __restrict__ ad_,
                            const float* __restrict__ RW)
{
    int node = blockIdx.x;
    int c = threadIdx.x;
    float x0 = d_px[node], x1 = d_py[node], x2 = d_pz[node];
    float hv = x0 * W[c] + x1 * W[128 + c] + x2 * W[256 + c];
    d_h1[node * 128 + c]   = hv;
    d_res1[node * 128 + c] = x0 * RW[c] + x1 * RW[128 + c] + x2 * RW[256 + c];

    __shared__ float r1[128], r2[128];
    r1[c] = hv * as_[c];
    r2[c] = hv * ad_[c];
    __syncthreads();
    for (int s = 64; s > 0; s >>= 1) {
        if (c < s) { r1[c] += r1[c + s]; r2[c] += r2[c + s]; }
        __syncthreads();
    }
    if (c == 0) { d_es[node] = r1[0]; d_ed[node] = r2[0]; }
}

// ---------------- 3b. GAT2 projection matmul (128 -> 256): g1 -> h2, res2 ----------------
__global__ void mm2_kernel(const float* __restrict__ W,
                           const float* __restrict__ RW)
{
    __shared__ float xs[8 * 128];
    int nb0 = blockIdx.x * 8;
    for (int i = threadIdx.x; i < 8 * 128; i += 256)
        xs[i] = d_g1[nb0 * 128 + i];
    __syncthreads();

    int c = threadIdx.x;
    float acc[8], ar[8];
#pragma unroll
    for (int r = 0; r < 8; r++) { acc[r] = 0.f; ar[r] = 0.f; }

    for (int i = 0; i < 128; i++) {
        float w  = W[i * 256 + c];
        float rw = RW[i * 256 + c];
#pragma unroll
        for (int r = 0; r < 8; r++) {
            float xv = xs[r * 128 + i];
            acc[r] += xv * w;
            ar[r]  += xv * rw;
        }
    }
#pragma unroll
    for (int r = 0; r < 8; r++) {
        int node = nb0 + r;
        d_h2[node * 256 + c]   = acc[r];
        d_res2[node * 256 + c] = ar[r];
    }
}

// ---------------- 3c. e_src/e_dst for GAT2 (from d_h2) ----------------
__global__ void e2_kernel(const float* __restrict__ as_,
                          const float* __restrict__ ad_)
{
    int node = blockIdx.x;
    int c = threadIdx.x;
    float hv = d_h2[node * 256 + c];
    __shared__ float r1[256], r2[256];
    r1[c] = hv * as_[c];
    r2[c] = hv * ad_[c];
    __syncthreads();
    for (int s = 128; s > 0; s >>= 1) {
        if (c < s) { r1[c] += r1[c + s]; r2[c] += r2[c + s]; }
        __syncthreads();
    }
    if (c == 0) { d_es[node] = r1[0]; d_ed[node] = r2[0]; }
}

// ---------------- 3d. attention aggregate (LAYER selects buffers device-side) ----------------
template <int LAYER, int C, bool RELU>
__global__ void attn_kernel(const float* __restrict__ bias)
{
    const float* __restrict__ h   = (LAYER == 1) ? d_h1   : d_h2;
    const float* __restrict__ res = (LAYER == 1) ? d_res1 : d_res2;
    float* __restrict__ out       = (LAYER == 1) ? d_g1   : d_g2;

    int gw   = (blockIdx.x * blockDim.x + threadIdx.x) >> 5;
    int lane = threadIdx.x & 31;
    if (gw >= BNc) return;
    int gn = gw;
    int b  = gn / Nc;

    float edv = d_ed[gn];
    float lg[Kc];
    int   nb[Kc];
#pragma unroll
    for (int k = 0; k < Kc; k++) {
        nb[k] = b * Nc + d_edges[gn * Kc + k];
        float e = d_es[nb[k]] + edv;
        lg[k] = (e > 0.f) ? e : 0.2f * e;
    }
    float m = lg[0];
#pragma unroll
    for (int k = 1; k < Kc; k++) m = fmaxf(m, lg[k]);
    float sum = 0.f;
#pragma unroll
    for (int k = 0; k < Kc; k++) { lg[k] = expf(lg[k] - m); sum += lg[k]; }
    float inv = 1.0f / sum;

    for (int c = lane; c < C; c += 32) {
        float acc = 0.f;
#pragma unroll
        for (int k = 0; k < Kc; k++) acc += lg[k] * h[nb[k] * C + c];
        float v = acc * inv + bias[c] + res[gn * C + c];
        out[gn * C + c] = RELU ? fmaxf(v, 0.f) : v;
    }
}

// ---------------- 4a. NetVLAD cluster softmax (reads d_g2) ----------------
__global__ void act_kernel(const float* __restrict__ cw,
                           const float* __restrict__ cb)
{
    __shared__ float xs[8 * 256];
    __shared__ float red[64];
    int nb0 = blockIdx.x * 8;
    for (int i = threadIdx.x; i < 8 * 256; i += 64)
        xs[i] = d_g2[nb0 * 256 + i];
    __syncthreads();

    int k = threadIdx.x;
    float acc[8];
#pragma unroll
    for (int r = 0; r < 8; r++) acc[r] = cb[k];
    for (int dd = 0; dd < 256; dd++) {
        float w = cw[dd * 64 + k];
#pragma unroll
        for (int r = 0; r < 8; r++) acc[r] += xs[r * 256 + dd] * w;
    }

#pragma unroll
    for (int r = 0; r < 8; r++) {
        red[k] = acc[r];
        __syncthreads();
        for (int s = 32; s > 0; s >>= 1) {
            if (k < s) red[k] = fmaxf(red[k], red[k + s]);
            __syncthreads();
        }
        float m = red[0];
        __syncthreads();
        float e = expf(acc[r] - m);
        red[k] = e;
        __syncthreads();
        for (int s = 32; s > 0; s >>= 1) {
            if (k < s) red[k] += red[k + s];
            __syncthreads();
        }
        float sum = red[0];
        __syncthreads();
        d_act[(nb0 + r) * 64 + k] = e / sum;
    }
}

// ---------------- 4b. vlad ----------------
__global__ void vlad_kernel(const float* __restrict__ cw2)
{
    int b = blockIdx.x >> 6;
    int k = blockIdx.x & 63;
    int dd = threadIdx.x;
    __shared__ float sa[256];
    float acc = 0.f, asum = 0.f;
    for (int n0 = 0; n0 < Nc; n0 += 256) {
        int lim = Nc - n0; if (lim > 256) lim = 256;
        if (threadIdx.x < lim)
            sa[threadIdx.x] = d_act[(b * Nc + n0 + threadIdx.x) * 64 + k];
        __syncthreads();
        for (int j = 0; j < lim; j++) {
            float a = sa[j];
            asum += a;
            acc  += a * d_g2[(b * Nc + n0 + j) * 256 + dd];
        }
        __syncthreads();
    }
    acc -= asum * cw2[dd * 64 + k];
    d_vlad[(b * 256 + dd) * 64 + k] = acc;
}

// ---------------- 4c. intra-normalize over d ----------------
__global__ void norm_kernel() {
    int b = blockIdx.x >> 6;
    int k = blockIdx.x & 63;
    int dd = threadIdx.x;
    float v = d_vlad[(b * 256 + dd) * 64 + k];
    __shared__ float red[256];
    red[dd] = v * v;
    __syncthreads();
    for (int s = 128; s > 0; s >>= 1) {
        if (dd < s) red[dd] += red[dd + s];
        __syncthreads();
    }
    float ss  = red[0];
    float den = fmaxf(sqrtf(ss), 1e-12f);
    d_vlad[(b * 256 + dd) * 64 + k] = v / den;
    if (dd == 0) d_colsq[b * 64 + k] = ss / (den * den);
}

// ---------------- 4d. hidden projection ----------------
__global__ void y_kernel(const float* __restrict__ h1w,
                         const float* __restrict__ h1b)
{
    int b = blockIdx.x;
    int o = threadIdx.x;
    __shared__ float red[64];
    __shared__ float gscale;
    if (o < 64) red[o] = d_colsq[b * 64 + o];
    __syncthreads();
    if (o == 0) {
        float s = 0.f;
        for (int i = 0; i < 64; i++) s += red[i];
        gscale = 1.0f / fmaxf(sqrtf(s), 1e-12f);
    }
    __syncthreads();

    __shared__ float sv[256];
    float acc = 0.f;
    for (int i0 = 0; i0 < 16384; i0 += 256) {
        sv[o] = d_vlad[b * 16384 + i0 + o];
        __syncthreads();
        for (int j = 0; j < 256; j++)
            acc += sv[j] * h1w[(i0 + j) * 256 + o];
        __syncthreads();
    }
    d_y[b * 256 + o] = acc * gscale + h1b[o];
}

// ---------------- 4e. context gating ----------------
__global__ void out_kernel(const float* __restrict__ gw,
                           const float* __restrict__ gb,
                           float* __restrict__ out)
{
    int b = blockIdx.x;
    int o = threadIdx.x;
    __shared__ float sy[256];
    sy[o] = d_y[b * 256 + o];
    __syncthreads();
    float acc = gb[o];
    for (int j = 0; j < 256; j++) acc += sy[j] * gw[j * 256 + o];
    float g = 1.0f / (1.0f + expf(-acc));
    out[b * 256 + o] = sy[o] * g;
}

// ---------------- launch (dict order confirmed by round-4 diagnostics) ----------------
extern "C" void kernel_launch(void* const* d_in, const int* in_sizes, int n_in,
                              void* d_out, int out_size) {
    const float* depth    = (const float*)d_in[1];
    const float* gat1_w   = (const float*)d_in[8];
    const float* gat1_as  = (const float*)d_in[9];
    const float* gat1_ad  = (const float*)d_in[10];
    const float* gat1_b   = (const float*)d_in[11];
    const float* gat1_res = (const float*)d_in[12];
    const float* gat2_w   = (const float*)d_in[13];
    const float* gat2_as  = (const float*)d_in[14];
    const float* gat2_ad  = (const float*)d_in[15];
    const float* gat2_b   = (const float*)d_in[16];
    const float* gat2_res = (const float*)d_in[17];
    const float* vlad_cw  = (const float*)d_in[18];
    const float* vlad_cb  = (const float*)d_in[19];
    const float* vlad_cw2 = (const float*)d_in[20];
    const float* vlad_h1w = (const float*)d_in[21];
    const float* vlad_h1b = (const float*)d_in[22];
    const float* gate_w   = (const float*)d_in[23];
    const float* gate_b   = (const float*)d_in[24];
    float* out = (float*)d_out;

    pts_kernel<<<(BNc + 255) / 256, 256>>>(depth);
    knn_kernel<<<Bc * 38, 256>>>();
    gat1_kernel<<<BNc, 128>>>(gat1_w, gat1_as, gat1_ad, gat1_res);
    attn_kernel<1, 128, true><<<BNc / 8, 256>>>(gat1_b);
    mm2_kernel<<<BNc / 8, 256>>>(gat2_w, gat2_res);
    e2_kernel<<<BNc, 256>>>(gat2_as, gat2_ad);
    attn_kernel<2, 256, false><<<BNc / 8, 256>>>(gat2_b);
    act_kernel<<<BNc / 8, 64>>>(vlad_cw, vlad_cb);
    vlad_kernel<<<Bc * 64, 256>>>(vlad_cw2);
    norm_kernel<<<Bc * 64, 256>>>();
    y_kernel<<<Bc, 256>>>(vlad_h1w, vlad_h1b);
    out_kernel<<<Bc, 256>>>(gate_w, gate_b, out);
}

// round 6
// speedup vs baseline: 2.4433x; 2.4433x over previous
#include <cuda_runtime.h>
#include <math.h>

#define Bc   2
#define Nc   9600
#define BNc  19200
#define Kc   10
#define DWc  150
#define PI_F 3.14159265358979323846f
#define NCH  40     // vlad N-chunks
#define CHN  240    // nodes per vlad chunk
#define YCH  16     // y-projection chunks

// ---------------- scratch (device-symbol access ONLY from device code) ----------------
__device__ float4 d_pts4[BNc];
__device__ int    d_edges[BNc * Kc];
__device__ float  d_h1[BNc * 128], d_res1[BNc * 128], d_g1[BNc * 128];
__device__ float  d_es[BNc], d_ed[BNc];
__device__ float  d_h2[BNc * 256], d_res2[BNc * 256], d_g2[BNc * 256];
__device__ float  d_act[BNc * 64];
__device__ float  d_vpart[Bc * NCH * 256 * 64];
__device__ float  d_vlad[Bc * 256 * 64];
__device__ float  d_colsq[Bc * 64];
__device__ float  d_ypart[Bc * YCH * 256];

// ---------------- 1. spherical -> cartesian ----------------
__global__ void pts_kernel(const float* __restrict__ depth) {
    int gn = blockIdx.x * 256 + threadIdx.x;
    if (gn >= BNc) return;
    int n = gn % Nc;
    int i = n / DWc;
    int j = n % DWc;
    float theta = -PI_F + (float)j * (2.0f * PI_F / 149.0f);
    float phi   = -0.5f * PI_F + (float)i * (PI_F / 63.0f);
    float r = depth[gn];
    float cp = cosf(phi), sp = sinf(phi);
    float st = sinf(theta), ct = cosf(theta);
    float x = r * cp * st;
    float y = r * sp;
    float z = r * cp * ct;
    d_pts4[gn] = make_float4(x, y, z, x * x + y * y + z * z);
}

// ---------------- 2. kNN: 4-way split-K, float4 tiles, exact (val,idx) merge ----------------
// grid = 300 (150 q-blocks per batch), block = 256. 64 queries/block, 4 threads/query.
__global__ void knn_kernel() {
    int b  = blockIdx.x / 150;
    int qb = blockIdx.x % 150;
    int t  = threadIdx.x;
    int ql = t >> 2;          // query within block (0..63)
    int h  = t & 3;           // candidate partition (c mod 4)
    int q  = qb * 64 + ql;
    int base = b * Nc;

    float4 qp = d_pts4[base + q];

    __shared__ float4 stile[480];
    __shared__ float  sval[64 * 4 * Kc];
    __shared__ int    sidx[64 * 4 * Kc];

    float bd[Kc]; int bi[Kc];
#pragma unroll
    for (int k = 0; k < Kc; k++) { bd[k] = 3.4e38f; bi[k] = -1; }
    float worst = 3.4e38f;

    for (int tile = 0; tile < 20; tile++) {
        int t0 = tile * 480;
        for (int i = t; i < 480; i += 256)
            stile[i] = d_pts4[base + t0 + i];
        __syncthreads();
#pragma unroll 4
        for (int cc = 0; cc < 120; cc++) {
            int c = cc * 4 + h;                     // interleaved partition, increasing index
            float4 p = stile[c];
            float d2 = qp.w + p.w - 2.0f * (qp.x * p.x + qp.y * p.y + qp.z * p.z);
            if (d2 < worst) {
                bd[Kc - 1] = d2; bi[Kc - 1] = t0 + c;
#pragma unroll
                for (int s = Kc - 1; s > 0; --s) {
                    if (bd[s] < bd[s - 1]) {
                        float td = bd[s]; bd[s] = bd[s - 1]; bd[s - 1] = td;
                        int   ti = bi[s]; bi[s] = bi[s - 1]; bi[s - 1] = ti;
                    }
                }
                worst = bd[Kc - 1];
            }
        }
        __syncthreads();
    }

    int lb = (ql * 4 + h) * Kc;
#pragma unroll
    for (int k = 0; k < Kc; k++) { sval[lb + k] = bd[k]; sidx[lb + k] = bi[k]; }
    __syncthreads();

    if (h == 0) {
        int p[4] = {0, 0, 0, 0};
        int lbase = ql * 4 * Kc;
#pragma unroll
        for (int outk = 0; outk < Kc; outk++) {
            float bv = 3.5e38f; int bix = 0x7fffffff; int bl = 0;
#pragma unroll
            for (int l = 0; l < 4; l++) {
                if (p[l] < Kc) {
                    float v = sval[lbase + l * Kc + p[l]];
                    int   ix = sidx[lbase + l * Kc + p[l]];
                    if (v < bv || (v == bv && ix < bix)) { bv = v; bix = ix; bl = l; }
                }
            }
            p[bl]++;
            d_edges[(base + q) * Kc + outk] = bix;
        }
    }
}

// ---------------- 3a. GAT1 (3->128): warp per node, fused e_src/e_dst ----------------
__global__ void gat1_kernel(const float* __restrict__ W,
                            const float* __restrict__ as_,
                            const float* __restrict__ ad_,
                            const float* __restrict__ RW)
{
    int gw   = (blockIdx.x * blockDim.x + threadIdx.x) >> 5;
    int lane = threadIdx.x & 31;
    if (gw >= BNc) return;
    float4 p = d_pts4[gw];
    float e1 = 0.f, e2 = 0.f;
#pragma unroll
    for (int i = 0; i < 4; i++) {
        int c = lane + i * 32;
        float hv = p.x * W[c] + p.y * W[128 + c] + p.z * W[256 + c];
        d_h1[gw * 128 + c]   = hv;
        d_res1[gw * 128 + c] = p.x * RW[c] + p.y * RW[128 + c] + p.z * RW[256 + c];
        e1 += hv * as_[c];
        e2 += hv * ad_[c];
    }
#pragma unroll
    for (int o = 16; o > 0; o >>= 1) {
        e1 += __shfl_down_sync(0xffffffffu, e1, o);
        e2 += __shfl_down_sync(0xffffffffu, e2, o);
    }
    if (lane == 0) { d_es[gw] = e1; d_ed[gw] = e2; }
}

// ---------------- 3b. attention aggregate (LAYER selects buffers device-side) ----------------
template <int LAYER, int C, bool RELU>
__global__ void attn_kernel(const float* __restrict__ bias)
{
    const float* __restrict__ h   = (LAYER == 1) ? d_h1   : d_h2;
    const float* __restrict__ res = (LAYER == 1) ? d_res1 : d_res2;
    float* __restrict__ out       = (LAYER == 1) ? d_g1   : d_g2;

    int gw   = (blockIdx.x * blockDim.x + threadIdx.x) >> 5;
    int lane = threadIdx.x & 31;
    if (gw >= BNc) return;
    int b = gw / Nc;

    float edv = d_ed[gw];
    float lg[Kc];
    int   nb[Kc];
#pragma unroll
    for (int k = 0; k < Kc; k++) {
        nb[k] = b * Nc + d_edges[gw * Kc + k];
        float e = d_es[nb[k]] + edv;
        lg[k] = (e > 0.f) ? e : 0.2f * e;
    }
    float m = lg[0];
#pragma unroll
    for (int k = 1; k < Kc; k++) m = fmaxf(m, lg[k]);
    float sum = 0.f;
#pragma unroll
    for (int k = 0; k < Kc; k++) { lg[k] = expf(lg[k] - m); sum += lg[k]; }
    float inv = 1.0f / sum;

    for (int c = lane; c < C; c += 32) {
        float acc = 0.f;
#pragma unroll
        for (int k = 0; k < Kc; k++) acc += lg[k] * h[nb[k] * C + c];
        float v = acc * inv + bias[c] + res[gw * C + c];
        out[gw * C + c] = RELU ? fmaxf(v, 0.f) : v;
    }
}

// ---------------- 3c. GAT2 matmul (128->256) fused with e_src/e_dst ----------------
__global__ void mm2_kernel(const float* __restrict__ W,
                           const float* __restrict__ RW,
                           const float* __restrict__ as_,
                           const float* __restrict__ ad_)
{
    __shared__ float xs[8 * 128];
    __shared__ float wred[2][8][8];
    int nb0 = blockIdx.x * 8;
    int t = threadIdx.x;
    for (int i = t; i < 8 * 128; i += 256)
        xs[i] = d_g1[nb0 * 128 + i];
    __syncthreads();

    int c = t;
    float acc[8], ar[8];
#pragma unroll
    for (int r = 0; r < 8; r++) { acc[r] = 0.f; ar[r] = 0.f; }

    for (int i = 0; i < 128; i++) {
        float w  = W[i * 256 + c];
        float rw = RW[i * 256 + c];
#pragma unroll
        for (int r = 0; r < 8; r++) {
            float xv = xs[r * 128 + i];
            acc[r] += xv * w;
            ar[r]  += xv * rw;
        }
    }

    float asv = as_[c], adv = ad_[c];
    int lane = t & 31, wid = t >> 5;
#pragma unroll
    for (int r = 0; r < 8; r++) {
        d_h2[(nb0 + r) * 256 + c]   = acc[r];
        d_res2[(nb0 + r) * 256 + c] = ar[r];
        float v1 = acc[r] * asv;
        float v2 = acc[r] * adv;
#pragma unroll
        for (int o = 16; o > 0; o >>= 1) {
            v1 += __shfl_down_sync(0xffffffffu, v1, o);
            v2 += __shfl_down_sync(0xffffffffu, v2, o);
        }
        if (lane == 0) { wred[0][r][wid] = v1; wred[1][r][wid] = v2; }
    }
    __syncthreads();
    if (t < 16) {
        int r = t & 7, which = t >> 3;
        float s = 0.f;
#pragma unroll
        for (int w = 0; w < 8; w++) s += wred[which][r][w];
        if (which == 0) d_es[nb0 + r] = s;
        else            d_ed[nb0 + r] = s;
    }
}

// ---------------- 4a. NetVLAD cluster softmax ----------------
__global__ void act_kernel(const float* __restrict__ cw,
                           const float* __restrict__ cb)
{
    __shared__ float xs[8 * 256];
    __shared__ float red[64];
    int nb0 = blockIdx.x * 8;
    for (int i = threadIdx.x; i < 8 * 256; i += 64)
        xs[i] = d_g2[nb0 * 256 + i];
    __syncthreads();

    int k = threadIdx.x;
    float acc[8];
#pragma unroll
    for (int r = 0; r < 8; r++) acc[r] = cb[k];
    for (int dd = 0; dd < 256; dd++) {
        float w = cw[dd * 64 + k];
#pragma unroll
        for (int r = 0; r < 8; r++) acc[r] += xs[r * 256 + dd] * w;
    }

#pragma unroll
    for (int r = 0; r < 8; r++) {
        red[k] = acc[r];
        __syncthreads();
        for (int s = 32; s > 0; s >>= 1) {
            if (k < s) red[k] = fmaxf(red[k], red[k + s]);
            __syncthreads();
        }
        float m = red[0];
        __syncthreads();
        float e = expf(acc[r] - m);
        red[k] = e;
        __syncthreads();
        for (int s = 32; s > 0; s >>= 1) {
            if (k < s) red[k] += red[k + s];
            __syncthreads();
        }
        float sum = red[0];
        __syncthreads();
        d_act[(nb0 + r) * 64 + k] = e / sum;
    }
}

// ---------------- 4b. vlad partial: outer-product GEMM over N-chunks ----------------
// grid = Bc*NCH, block = 1024. thread: d = t&255, k-group = t>>8 (16 k's each).
__global__ void vlad_partial() {
    int b  = blockIdx.x / NCH;
    int ch = blockIdx.x % NCH;
    int t  = threadIdx.x;
    int d  = t & 255;
    int kg = t >> 8;
    int base = b * Nc + ch * CHN;

    __shared__ float sact[16 * 64];
    float acc[16];
#pragma unroll
    for (int j = 0; j < 16; j++) acc[j] = 0.f;

    int nl = t >> 6, kk = t & 63;
    for (int n0 = 0; n0 < CHN; n0 += 16) {
        sact[t] = d_act[(base + n0 + nl) * 64 + kk];
        __syncthreads();
#pragma unroll
        for (int j = 0; j < 16; j++) {
            float g = d_g2[(base + n0 + j) * 256 + d];
            const float4* arow = (const float4*)&sact[j * 64 + kg * 16];
            float4 a0 = arow[0], a1 = arow[1], a2 = arow[2], a3 = arow[3];
            acc[0]  += g * a0.x; acc[1]  += g * a0.y; acc[2]  += g * a0.z; acc[3]  += g * a0.w;
            acc[4]  += g * a1.x; acc[5]  += g * a1.y; acc[6]  += g * a1.z; acc[7]  += g * a1.w;
            acc[8]  += g * a2.x; acc[9]  += g * a2.y; acc[10] += g * a2.z; acc[11] += g * a2.w;
            acc[12] += g * a3.x; acc[13] += g * a3.y; acc[14] += g * a3.z; acc[15] += g * a3.w;
        }
        __syncthreads();
    }

    float4* dst = (float4*)&d_vpart[(((b * NCH) + ch) * 256 + d) * 64 + kg * 16];
    dst[0] = make_float4(acc[0],  acc[1],  acc[2],  acc[3]);
    dst[1] = make_float4(acc[4],  acc[5],  acc[6],  acc[7]);
    dst[2] = make_float4(acc[8],  acc[9],  acc[10], acc[11]);
    dst[3] = make_float4(acc[12], acc[13], acc[14], acc[15]);
}

// ---------------- 4c. vlad finish: asum + combine + cw2 + intra-norm + colsq ----------------
__global__ void vlad_finish(const float* __restrict__ cw2) {
    int b  = blockIdx.x >> 6;
    int k  = blockIdx.x & 63;
    int dd = threadIdx.x;

    float part = 0.f;
    for (int n = dd; n < Nc; n += 256)
        part += d_act[(b * Nc + n) * 64 + k];
    __shared__ float red[256];
    red[dd] = part;
    __syncthreads();
    for (int s = 128; s > 0; s >>= 1) {
        if (dd < s) red[dd] += red[dd + s];
        __syncthreads();
    }
    float asum = red[0];
    __syncthreads();

    float v = 0.f;
#pragma unroll 8
    for (int ch = 0; ch < NCH; ch++)
        v += d_vpart[((b * NCH + ch) * 256 + dd) * 64 + k];
    v -= asum * cw2[dd * 64 + k];

    red[dd] = v * v;
    __syncthreads();
    for (int s = 128; s > 0; s >>= 1) {
        if (dd < s) red[dd] += red[dd + s];
        __syncthreads();
    }
    float ss  = red[0];
    float den = fmaxf(sqrtf(ss), 1e-12f);
    d_vlad[(b * 256 + dd) * 64 + k] = v / den;
    if (dd == 0) d_colsq[b * 64 + k] = ss / (den * den);
}

// ---------------- 4d. y partial projection ----------------
__global__ void y_partial(const float* __restrict__ h1w) {
    int b  = blockIdx.x / YCH;
    int ch = blockIdx.x % YCH;
    int o  = threadIdx.x;
    __shared__ float sv[1024];
    for (int i = o; i < 1024; i += 256)
        sv[i] = d_vlad[b * 16384 + ch * 1024 + i];
    __syncthreads();
    float acc = 0.f;
#pragma unroll 4
    for (int j = 0; j < 1024; j++)
        acc += sv[j] * h1w[(ch * 1024 + j) * 256 + o];
    d_ypart[(b * YCH + ch) * 256 + o] = acc;
}

// ---------------- 4e. reduce y + gate + output ----------------
__global__ void out_kernel(const float* __restrict__ h1b,
                           const float* __restrict__ gw,
                           const float* __restrict__ gb,
                           float* __restrict__ out)
{
    int b = blockIdx.x;
    int o = threadIdx.x;
    __shared__ float sc[64];
    __shared__ float gs;
    if (o < 64) sc[o] = d_colsq[b * 64 + o];
    __syncthreads();
    if (o == 0) {
        float s = 0.f;
        for (int i = 0; i < 64; i++) s += sc[i];
        gs = 1.0f / fmaxf(sqrtf(s), 1e-12f);
    }
    __syncthreads();

    float acc = 0.f;
#pragma unroll
    for (int ch = 0; ch < YCH; ch++)
        acc += d_ypart[(b * YCH + ch) * 256 + o];
    float y = acc * gs + h1b[o];

    __shared__ float sy[256];
    sy[o] = y;
    __syncthreads();
    float g = gb[o];
    for (int j = 0; j < 256; j++) g += sy[j] * gw[j * 256 + o];
    out[b * 256 + o] = y * (1.0f / (1.0f + expf(-g)));
}

// ---------------- launch ----------------
extern "C" void kernel_launch(void* const* d_in, const int* in_sizes, int n_in,
                              void* d_out, int out_size) {
    const float* depth    = (const float*)d_in[1];
    const float* gat1_w   = (const float*)d_in[8];
    const float* gat1_as  = (const float*)d_in[9];
    const float* gat1_ad  = (const float*)d_in[10];
    const float* gat1_b   = (const float*)d_in[11];
    const float* gat1_res = (const float*)d_in[12];
    const float* gat2_w   = (const float*)d_in[13];
    const float* gat2_as  = (const float*)d_in[14];
    const float* gat2_ad  = (const float*)d_in[15];
    const float* gat2_b   = (const float*)d_in[16];
    const float* gat2_res = (const float*)d_in[17];
    const float* vlad_cw  = (const float*)d_in[18];
    const float* vlad_cb  = (const float*)d_in[19];
    const float* vlad_cw2 = (const float*)d_in[20];
    const float* vlad_h1w = (const float*)d_in[21];
    const float* vlad_h1b = (const float*)d_in[22];
    const float* gate_w   = (const float*)d_in[23];
    const float* gate_b   = (const float*)d_in[24];
    float* out = (float*)d_out;

    pts_kernel<<<75, 256>>>(depth);
    knn_kernel<<<300, 256>>>();
    gat1_kernel<<<2400, 256>>>(gat1_w, gat1_as, gat1_ad, gat1_res);
    attn_kernel<1, 128, true><<<2400, 256>>>(gat1_b);
    mm2_kernel<<<2400, 256>>>(gat2_w, gat2_res, gat2_as, gat2_ad);
    attn_kernel<2, 256, false><<<2400, 256>>>(gat2_b);
    act_kernel<<<2400, 64>>>(vlad_cw, vlad_cb);
    vlad_partial<<<Bc * NCH, 1024>>>();
    vlad_finish<<<Bc * 64, 256>>>(vlad_cw2);
    y_partial<<<Bc * YCH, 256>>>(vlad_h1w);
    out_kernel<<<Bc, 256>>>(vlad_h1b, gate_w, gate_b, out);
}

// round 7
// speedup vs baseline: 2.7940x; 1.1435x over previous
#include <cuda_runtime.h>
#include <math.h>

#define Bc   2
#define Nc   9600
#define BNc  19200
#define Kc   10
#define DWc  150
#define PI_F 3.14159265358979323846f
#define NCH  75     // vlad N-chunks
#define CHN  128    // nodes per vlad chunk
#define YCH  64     // y-projection chunks

// ---------------- scratch (device-symbol access ONLY from device code) ----------------
__device__ float4 d_pts4[BNc];
__device__ int    d_edges[BNc * Kc];
__device__ float  d_h1[BNc * 128], d_res1[BNc * 128], d_g1[BNc * 128];
__device__ float  d_es[BNc], d_ed[BNc];
__device__ float  d_h2[BNc * 256], d_res2[BNc * 256], d_g2[BNc * 256];
__device__ float  d_act[BNc * 64];
__device__ float  d_vpart[Bc * NCH * 256 * 64];
__device__ float  d_vlad[Bc * 256 * 64];
__device__ float  d_colsq[Bc * 64];
__device__ float  d_ypart[Bc * YCH * 256];
__device__ float  d_nopbuf[4];

// ---------------- 0. nop (shifts knn to 4th launch so ncu -s5-c1 profiles knn) --------
__global__ void nop_kernel(int which) {
    if ((int)blockIdx.x == (int)gridDim.x)   // never true; opaque to compiler
        d_nopbuf[which] = 1.0f;
}

// ---------------- 1. spherical -> cartesian ----------------
__global__ void pts_kernel(const float* __restrict__ depth) {
    int gn = blockIdx.x * 256 + threadIdx.x;
    if (gn >= BNc) return;
    int n = gn % Nc;
    int i = n / DWc;
    int j = n % DWc;
    float theta = -PI_F + (float)j * (2.0f * PI_F / 149.0f);
    float phi   = -0.5f * PI_F + (float)i * (PI_F / 63.0f);
    float r = depth[gn];
    float cp = cosf(phi), sp = sinf(phi);
    float st = sinf(theta), ct = cosf(theta);
    float x = r * cp * st;
    float y = r * sp;
    float z = r * cp * ct;
    d_pts4[gn] = make_float4(x, y, z, x * x + y * y + z * z);
}

// ---------------- 2. kNN: 4-way split-K, grouped-4 test, exact (val,idx) merge --------
// grid = 300 (150 q-blocks per batch), block = 256. 64 queries/block, 4 threads/query.
// Score s = |c|^2 - 2 q.c  (drops per-query constant |q|^2: ordering-invariant).
__global__ void knn_kernel() {
    int b  = blockIdx.x / 150;
    int qb = blockIdx.x % 150;
    int t  = threadIdx.x;
    int ql = t >> 2;          // query within block (0..63)
    int h  = t & 3;           // candidate partition (c mod 4)
    int q  = qb * 64 + ql;
    int base = b * Nc;

    float4 qp = d_pts4[base + q];

    __shared__ float4 stile[480];
    __shared__ float  sval[64 * 4 * Kc];
    __shared__ int    sidx[64 * 4 * Kc];

    float bd[Kc]; int bi[Kc];
#pragma unroll
    for (int k = 0; k < Kc; k++) { bd[k] = 3.4e38f; bi[k] = -1; }
    float worst = 3.4e38f;

    for (int tile = 0; tile < 20; tile++) {
        int t0 = tile * 480;
        for (int i = t; i < 480; i += 256)
            stile[i] = d_pts4[base + t0 + i];
        __syncthreads();
        for (int cc = 0; cc < 120; cc += 4) {
            float s0, s1, s2, s3;
            {
                float4 p = stile[(cc + 0) * 4 + h];
                s0 = fmaf(-2.0f, fmaf(qp.x, p.x, fmaf(qp.y, p.y, qp.z * p.z)), p.w);
                p = stile[(cc + 1) * 4 + h];
                s1 = fmaf(-2.0f, fmaf(qp.x, p.x, fmaf(qp.y, p.y, qp.z * p.z)), p.w);
                p = stile[(cc + 2) * 4 + h];
                s2 = fmaf(-2.0f, fmaf(qp.x, p.x, fmaf(qp.y, p.y, qp.z * p.z)), p.w);
                p = stile[(cc + 3) * 4 + h];
                s3 = fmaf(-2.0f, fmaf(qp.x, p.x, fmaf(qp.y, p.y, qp.z * p.z)), p.w);
            }
            float m4 = fminf(fminf(s0, s1), fminf(s2, s3));
            if (m4 < worst) {
                float sv[4] = {s0, s1, s2, s3};
#pragma unroll
                for (int u = 0; u < 4; u++) {
                    float d2 = sv[u];
                    if (d2 < worst) {
                        bd[Kc - 1] = d2; bi[Kc - 1] = t0 + (cc + u) * 4 + h;
#pragma unroll
                        for (int s = Kc - 1; s > 0; --s) {
                            if (bd[s] < bd[s - 1]) {
                                float td = bd[s]; bd[s] = bd[s - 1]; bd[s - 1] = td;
                                int   ti = bi[s]; bi[s] = bi[s - 1]; bi[s - 1] = ti;
                            }
                        }
                        worst = bd[Kc - 1];
                    }
                }
            }
        }
        __syncthreads();
    }

    int lb = (ql * 4 + h) * Kc;
#pragma unroll
    for (int k = 0; k < Kc; k++) { sval[lb + k] = bd[k]; sidx[lb + k] = bi[k]; }
    __syncthreads();

    if (h == 0) {
        int p[4] = {0, 0, 0, 0};
        int lbase = ql * 4 * Kc;
#pragma unroll
        for (int outk = 0; outk < Kc; outk++) {
            float bv = 3.5e38f; int bix = 0x7fffffff; int bl = 0;
#pragma unroll
            for (int l = 0; l < 4; l++) {
                if (p[l] < Kc) {
                    float v = sval[lbase + l * Kc + p[l]];
                    int   ix = sidx[lbase + l * Kc + p[l]];
                    if (v < bv || (v == bv && ix < bix)) { bv = v; bix = ix; bl = l; }
                }
            }
            p[bl]++;
            d_edges[(base + q) * Kc + outk] = bix;
        }
    }
}

// ---------------- 3a. GAT1 (3->128): warp per node, fused e_src/e_dst ----------------
__global__ void gat1_kernel(const float* __restrict__ W,
                            const float* __restrict__ as_,
                            const float* __restrict__ ad_,
                            const float* __restrict__ RW)
{
    int gw   = (blockIdx.x * blockDim.x + threadIdx.x) >> 5;
    int lane = threadIdx.x & 31;
    if (gw >= BNc) return;
    float4 p = d_pts4[gw];
    float e1 = 0.f, e2 = 0.f;
#pragma unroll
    for (int i = 0; i < 4; i++) {
        int c = lane + i * 32;
        float hv = p.x * W[c] + p.y * W[128 + c] + p.z * W[256 + c];
        d_h1[gw * 128 + c]   = hv;
        d_res1[gw * 128 + c] = p.x * RW[c] + p.y * RW[128 + c] + p.z * RW[256 + c];
        e1 += hv * as_[c];
        e2 += hv * ad_[c];
    }
#pragma unroll
    for (int o = 16; o > 0; o >>= 1) {
        e1 += __shfl_down_sync(0xffffffffu, e1, o);
        e2 += __shfl_down_sync(0xffffffffu, e2, o);
    }
    if (lane == 0) { d_es[gw] = e1; d_ed[gw] = e2; }
}

// ---------------- 3b. attention aggregate (LAYER selects buffers device-side) ----------
template <int LAYER, int C, bool RELU>
__global__ void attn_kernel(const float* __restrict__ bias)
{
    const float* __restrict__ h   = (LAYER == 1) ? d_h1   : d_h2;
    const float* __restrict__ res = (LAYER == 1) ? d_res1 : d_res2;
    float* __restrict__ out       = (LAYER == 1) ? d_g1   : d_g2;

    int gw   = (blockIdx.x * blockDim.x + threadIdx.x) >> 5;
    int lane = threadIdx.x & 31;
    if (gw >= BNc) return;
    int b = gw / Nc;

    float edv = d_ed[gw];
    float lg[Kc];
    int   nb[Kc];
#pragma unroll
    for (int k = 0; k < Kc; k++) {
        nb[k] = b * Nc + d_edges[gw * Kc + k];
        float e = d_es[nb[k]] + edv;
        lg[k] = (e > 0.f) ? e : 0.2f * e;
    }
    float m = lg[0];
#pragma unroll
    for (int k = 1; k < Kc; k++) m = fmaxf(m, lg[k]);
    float sum = 0.f;
#pragma unroll
    for (int k = 0; k < Kc; k++) { lg[k] = expf(lg[k] - m); sum += lg[k]; }
    float inv = 1.0f / sum;

    for (int c = lane; c < C; c += 32) {
        float acc = 0.f;
#pragma unroll
        for (int k = 0; k < Kc; k++) acc += lg[k] * h[nb[k] * C + c];
        float v = acc * inv + bias[c] + res[gw * C + c];
        out[gw * C + c] = RELU ? fmaxf(v, 0.f) : v;
    }
}

// ---------------- 3c. GAT2 matmul (128->256), 16 nodes/block, fused e_src/e_dst -------
__global__ void mm2_kernel(const float* __restrict__ W,
                           const float* __restrict__ RW,
                           const float* __restrict__ as_,
                           const float* __restrict__ ad_)
{
    __shared__ float xs[16 * 128];
    __shared__ float wred[2][16][8];
    int nb0 = blockIdx.x * 16;
    int t = threadIdx.x;
    for (int i = t; i < 16 * 128; i += 256)
        xs[i] = d_g1[nb0 * 128 + i];
    __syncthreads();

    int c = t;
    float acc[16], ar[16];
#pragma unroll
    for (int r = 0; r < 16; r++) { acc[r] = 0.f; ar[r] = 0.f; }

    for (int i = 0; i < 128; i++) {
        float w  = W[i * 256 + c];
        float rw = RW[i * 256 + c];
#pragma unroll
        for (int r = 0; r < 16; r++) {
            float xv = xs[r * 128 + i];
            acc[r] += xv * w;
            ar[r]  += xv * rw;
        }
    }

    float asv = as_[c], adv = ad_[c];
    int lane = t & 31, wid = t >> 5;
#pragma unroll
    for (int r = 0; r < 16; r++) {
        d_h2[(nb0 + r) * 256 + c]   = acc[r];
        d_res2[(nb0 + r) * 256 + c] = ar[r];
        float v1 = acc[r] * asv;
        float v2 = acc[r] * adv;
#pragma unroll
        for (int o = 16; o > 0; o >>= 1) {
            v1 += __shfl_down_sync(0xffffffffu, v1, o);
            v2 += __shfl_down_sync(0xffffffffu, v2, o);
        }
        if (lane == 0) { wred[0][r][wid] = v1; wred[1][r][wid] = v2; }
    }
    __syncthreads();
    if (t < 32) {
        int r = t & 15, which = t >> 4;
        float s = 0.f;
#pragma unroll
        for (int w = 0; w < 8; w++) s += wred[which][r][w];
        if (which == 0) d_es[nb0 + r] = s;
        else            d_ed[nb0 + r] = s;
    }
}

// ---------------- 4a. NetVLAD cluster softmax ----------------
__global__ void act_kernel(const float* __restrict__ cw,
                           const float* __restrict__ cb)
{
    __shared__ float xs[8 * 256];
    __shared__ float red[64];
    int nb0 = blockIdx.x * 8;
    for (int i = threadIdx.x; i < 8 * 256; i += 64)
        xs[i] = d_g2[nb0 * 256 + i];
    __syncthreads();

    int k = threadIdx.x;
    float acc[8];
#pragma unroll
    for (int r = 0; r < 8; r++) acc[r] = cb[k];
    for (int dd = 0; dd < 256; dd++) {
        float w = cw[dd * 64 + k];
#pragma unroll
        for (int r = 0; r < 8; r++) acc[r] += xs[r * 256 + dd] * w;
    }

#pragma unroll
    for (int r = 0; r < 8; r++) {
        red[k] = acc[r];
        __syncthreads();
        for (int s = 32; s > 0; s >>= 1) {
            if (k < s) red[k] = fmaxf(red[k], red[k + s]);
            __syncthreads();
        }
        float m = red[0];
        __syncthreads();
        float e = expf(acc[r] - m);
        red[k] = e;
        __syncthreads();
        for (int s = 32; s > 0; s >>= 1) {
            if (k < s) red[k] += red[k + s];
            __syncthreads();
        }
        float sum = red[0];
        __syncthreads();
        d_act[(nb0 + r) * 64 + k] = e / sum;
    }
}

// ---------------- 4b. vlad partial: outer-product GEMM over N-chunks ----------------
// grid = Bc*NCH (=150), block = 1024. thread: d = t&255, k-group = t>>8 (16 k's each).
__global__ void vlad_partial() {
    int b  = blockIdx.x / NCH;
    int ch = blockIdx.x % NCH;
    int t  = threadIdx.x;
    int d  = t & 255;
    int kg = t >> 8;
    int base = b * Nc + ch * CHN;

    __shared__ float sact[16 * 64];
    float acc[16];
#pragma unroll
    for (int j = 0; j < 16; j++) acc[j] = 0.f;

    int nl = t >> 6, kk = t & 63;
    for (int n0 = 0; n0 < CHN; n0 += 16) {
        sact[t] = d_act[(base + n0 + nl) * 64 + kk];
        __syncthreads();
#pragma unroll
        for (int j = 0; j < 16; j++) {
            float g = d_g2[(base + n0 + j) * 256 + d];
            const float4* arow = (const float4*)&sact[j * 64 + kg * 16];
            float4 a0 = arow[0], a1 = arow[1], a2 = arow[2], a3 = arow[3];
            acc[0]  += g * a0.x; acc[1]  += g * a0.y; acc[2]  += g * a0.z; acc[3]  += g * a0.w;
            acc[4]  += g * a1.x; acc[5]  += g * a1.y; acc[6]  += g * a1.z; acc[7]  += g * a1.w;
            acc[8]  += g * a2.x; acc[9]  += g * a2.y; acc[10] += g * a2.z; acc[11] += g * a2.w;
            acc[12] += g * a3.x; acc[13] += g * a3.y; acc[14] += g * a3.z; acc[15] += g * a3.w;
        }
        __syncthreads();
    }

    float4* dst = (float4*)&d_vpart[(((b * NCH) + ch) * 256 + d) * 64 + kg * 16];
    dst[0] = make_float4(acc[0],  acc[1],  acc[2],  acc[3]);
    dst[1] = make_float4(acc[4],  acc[5],  acc[6],  acc[7]);
    dst[2] = make_float4(acc[8],  acc[9],  acc[10], acc[11]);
    dst[3] = make_float4(acc[12], acc[13], acc[14], acc[15]);
}

// ---------------- 4c. vlad finish: asum + combine + cw2 + intra-norm + colsq ----------
__global__ void vlad_finish(const float* __restrict__ cw2) {
    int b  = blockIdx.x >> 6;
    int k  = blockIdx.x & 63;
    int dd = threadIdx.x;

    float part = 0.f;
    for (int n = dd; n < Nc; n += 256)
        part += d_act[(b * Nc + n) * 64 + k];
    __shared__ float red[256];
    red[dd] = part;
    __syncthreads();
    for (int s = 128; s > 0; s >>= 1) {
        if (dd < s) red[dd] += red[dd + s];
        __syncthreads();
    }
    float asum = red[0];
    __syncthreads();

    float v = 0.f;
#pragma unroll 5
    for (int ch = 0; ch < NCH; ch++)
        v += d_vpart[((b * NCH + ch) * 256 + dd) * 64 + k];
    v -= asum * cw2[dd * 64 + k];

    red[dd] = v * v;
    __syncthreads();
    for (int s = 128; s > 0; s >>= 1) {
        if (dd < s) red[dd] += red[dd + s];
        __syncthreads();
    }
    float ss  = red[0];
    float den = fmaxf(sqrtf(ss), 1e-12f);
    d_vlad[(b * 256 + dd) * 64 + k] = v / den;
    if (dd == 0) d_colsq[b * 64 + k] = ss / (den * den);
}

// ---------------- 4d. y partial projection ----------------
__global__ void y_partial(const float* __restrict__ h1w) {
    int b  = blockIdx.x / YCH;
    int ch = blockIdx.x % YCH;
    int o  = threadIdx.x;
    __shared__ float sv[256];
    sv[o] = d_vlad[b * 16384 + ch * 256 + o];
    __syncthreads();
    float acc = 0.f;
#pragma unroll 4
    for (int j = 0; j < 256; j++)
        acc += sv[j] * h1w[(ch * 256 + j) * 256 + o];
    d_ypart[(b * YCH + ch) * 256 + o] = acc;
}

// ---------------- 4e. reduce y + gate + output ----------------
__global__ void out_kernel(const float* __restrict__ h1b,
                           const float* __restrict__ gw,
                           const float* __restrict__ gb,
                           float* __restrict__ out)
{
    int b = blockIdx.x;
    int o = threadIdx.x;
    __shared__ float sc[64];
    __shared__ float gs;
    if (o < 64) sc[o] = d_colsq[b * 64 + o];
    __syncthreads();
    if (o == 0) {
        float s = 0.f;
        for (int i = 0; i < 64; i++) s += sc[i];
        gs = 1.0f / fmaxf(sqrtf(s), 1e-12f);
    }
    __syncthreads();

    float acc = 0.f;
#pragma unroll
    for (int ch = 0; ch < YCH; ch++)
        acc += d_ypart[(b * YCH + ch) * 256 + o];
    float y = acc * gs + h1b[o];

    __shared__ float sy[256];
    sy[o] = y;
    __syncthreads();
    float g = gb[o];
    for (int j = 0; j < 256; j++) g += sy[j] * gw[j * 256 + o];
    out[b * 256 + o] = y * (1.0f / (1.0f + expf(-g)));
}

// ---------------- launch ----------------
extern "C" void kernel_launch(void* const* d_in, const int* in_sizes, int n_in,
                              void* d_out, int out_size) {
    const float* depth    = (const float*)d_in[1];
    const float* gat1_w   = (const float*)d_in[8];
    const float* gat1_as  = (const float*)d_in[9];
    const float* gat1_ad  = (const float*)d_in[10];
    const float* gat1_b   = (const float*)d_in[11];
    const float* gat1_res = (const float*)d_in[12];
    const float* gat2_w   = (const float*)d_in[13];
    const float* gat2_as  = (const float*)d_in[14];
    const float* gat2_ad  = (const float*)d_in[15];
    const float* gat2_b   = (const float*)d_in[16];
    const float* gat2_res = (const float*)d_in[17];
    const float* vlad_cw  = (const float*)d_in[18];
    const float* vlad_cb  = (const float*)d_in[19];
    const float* vlad_cw2 = (const float*)d_in[20];
    const float* vlad_h1w = (const float*)d_in[21];
    const float* vlad_h1b = (const float*)d_in[22];
    const float* gate_w   = (const float*)d_in[23];
    const float* gate_b   = (const float*)d_in[24];
    float* out = (float*)d_out;

    pts_kernel<<<75, 256>>>(depth);
    nop_kernel<<<1, 32>>>(0);            // position shims: make knn the 4th launch
    nop_kernel<<<1, 32>>>(1);            // (ncu -s5-c1 has profiled launch #4 each round)
    knn_kernel<<<300, 256>>>();
    gat1_kernel<<<2400, 256>>>(gat1_w, gat1_as, gat1_ad, gat1_res);
    attn_kernel<1, 128, true><<<2400, 256>>>(gat1_b);
    mm2_kernel<<<1200, 256>>>(gat2_w, gat2_res, gat2_as, gat2_ad);
    attn_kernel<2, 256, false><<<2400, 256>>>(gat2_b);
    act_kernel<<<2400, 64>>>(vlad_cw, vlad_cb);
    vlad_partial<<<Bc * NCH, 1024>>>();
    vlad_finish<<<Bc * 64, 256>>>(vlad_cw2);
    y_partial<<<Bc * YCH, 256>>>(vlad_h1w);
    out_kernel<<<Bc, 256>>>(vlad_h1b, gate_w, gate_b, out);
}